// round 12
// baseline (speedup 1.0000x reference)
#include <cuda_runtime.h>
#include <cstdint>

// NMS_5549097746496: fused 8x8x8 MaxPool -> MaxUnpool -> threshold(0.5) -> (thresholded == x)
// Input:  raw [2,3,128,256,256] fp32 ; Output: mask as float32 0/1.
//
// out[i] = (x[i]==0) ? 1 : 0 everywhere, EXCEPT the block-argmax position when
// bmax > 0.5, which is 1 (the unpooled value there is bit-identical to x).
// Phase 1 streams (x==0); phase 2 overwrites one element per hot window
// (same-thread program order -> correctly ordered).
//
// R12 change: depth-2 plane pipeline (3 buffers of 8 x float4).
//   prologue: load planes 0,1 ; iter i: issue plane i+2 loads, process plane i.
// Steady state keeps 16 loads in flight AT ALL TIMES (R10's burst drained 16->0;
// R11's 1-ahead pipeline held only 8 -> regressed). Regs ~112 -> 4 CTAs/SM;
// R5-R11 evidence: outstanding-load count, not occupancy, is the lever.
//
// Layout (= R7/R10, measured L1~42%): CTA = 128 thr = 4 warps; tile 8d x 8h x 256w.
//   warp : 0..3, owns a 64-float w-span (8 windows)
//   lane : win = lane>>2 (window), dzh = (lane>>1)&1 (dz half), wc = lane&1
// Per load instruction: 2 dz-planes x 256B contiguous = 4 fully-used 128B lines.

#define NMS_THRESH 0.5f

__global__ __launch_bounds__(128, 4)
void nms_mask_kernel(const float* __restrict__ in, float* __restrict__ out) {
    const int W = 256;
    const int HW = 256 * 256;

    int bid  = blockIdx.x;        // 6 * 16 * 32 = 3072
    int hblk = bid & 31;          // 32 h-windows
    int dblk = (bid >> 5) & 15;   // 16 d-windows
    int bc   = bid >> 9;          // 6

    int lane = threadIdx.x & 31;
    int warp = threadIdx.x >> 5;  // 0..3, w-span
    int win  = lane >> 2;         // 0..7  window within warp span
    int dzh  = (lane >> 1) & 1;   // 0..1  dz half (dz = dzh*4 + dzl)
    int wc   = lane & 1;          // 0..1  16B chunk within window row

    // window-origin offset (dz=0,dy=0,dx=0) for this lane's window
    size_t wbase = ((size_t)(bc * 128 + dblk * 8)) * HW
                 + (size_t)(hblk * 8) * W
                 + (size_t)(warp * 64 + win * 8);
    // this lane's chunk base
    size_t mybase = wbase + (size_t)dzh * 4 * HW + (size_t)wc * 4;

    const float* p = in  + mybase;
    float*       q = out + mybase;

    float best  = __int_as_float(0xff800000);  // -inf
    int   bestE = 1 << 30;

    float4 buf[3][8];

    // ---- prologue: load planes 0 and 1 (16 independent LDG.128 in flight) ----
    #pragma unroll
    for (int dy = 0; dy < 8; dy++)
        buf[0][dy] = __ldcs(reinterpret_cast<const float4*>(p + 0 * HW + dy * W));
    #pragma unroll
    for (int dy = 0; dy < 8; dy++)
        buf[1][dy] = __ldcs(reinterpret_cast<const float4*>(p + 1 * HW + dy * W));

    // ---- depth-2 pipelined mainloop over this lane's 4 dz-planes ----
    #pragma unroll
    for (int dzl = 0; dzl < 4; dzl++) {
        const int cur = dzl % 3;          // constant-folded under full unroll
        const int nxt = (dzl + 2) % 3;

        // issue plane dzl+2's loads; planes dzl+1 and dzl+2 now pending
        if (dzl < 2) {
            #pragma unroll
            for (int dy = 0; dy < 8; dy++)
                buf[nxt][dy] = __ldcs(reinterpret_cast<const float4*>(
                                   p + (dzl + 2) * HW + dy * W));
        }

        // process current plane: emit mask + update running (max, argE)
        #pragma unroll
        for (int dy = 0; dy < 8; dy++) {
            float4 x = buf[cur][dy];
            float4 m;
            m.x = (x.x == 0.0f) ? 1.0f : 0.0f;
            m.y = (x.y == 0.0f) ? 1.0f : 0.0f;
            m.z = (x.z == 0.0f) ? 1.0f : 0.0f;
            m.w = (x.w == 0.0f) ? 1.0f : 0.0f;
            __stcs(reinterpret_cast<float4*>(q + dzl * HW + dy * W), m);

            int eb = (dzh * 4 + dzl) * 64 + dy * 8 + wc * 4;  // K-index of x.x
            // full lexicographic comparator (value desc, e asc) -> order-independent
            if (x.x > best || (x.x == best && eb + 0 < bestE)) { best = x.x; bestE = eb + 0; }
            if (x.y > best || (x.y == best && eb + 1 < bestE)) { best = x.y; bestE = eb + 1; }
            if (x.z > best || (x.z == best && eb + 2 < bestE)) { best = x.z; bestE = eb + 2; }
            if (x.w > best || (x.w == best && eb + 3 < bestE)) { best = x.w; bestE = eb + 3; }
        }
    }

    // remember local candidate to identify the owning lane afterwards
    float lbest = best; int lE = bestE;

    // reduce across the 4 lanes of this window (xor 1,2 stays in aligned group of 4)
    #pragma unroll
    for (int msk = 1; msk < 4; msk <<= 1) {
        float ov = __shfl_xor_sync(0xffffffffu, best,  msk);
        int   oe = __shfl_xor_sync(0xffffffffu, bestE, msk);
        if (ov > best || (ov == best && oe < bestE)) { best = ov; bestE = oe; }
    }

    // phase 2: the lane that loaded the winning element rewrites it to 1.0 if hot.
    // K-index e is unique across the window, so exactly one lane matches.
    if (best > NMS_THRESH && lbest == best && lE == bestE) {
        int dz = bestE >> 6, dy = (bestE >> 3) & 7, dx = bestE & 7;
        out[wbase + (size_t)dz * HW + (size_t)dy * W + dx] = 1.0f;
    }
}

extern "C" void kernel_launch(void* const* d_in, const int* in_sizes, int n_in,
                              void* d_out, int out_size) {
    (void)in_sizes; (void)n_in; (void)out_size;
    const float* in = (const float*)d_in[0];
    float* out = (float*)d_out;
    // bc(6) * dblk(16) * hblk(32) = 3072 CTAs, 128 threads each
    nms_mask_kernel<<<3072, 128>>>(in, out);
}

// round 13
// speedup vs baseline: 1.0381x; 1.0381x over previous
#include <cuda_runtime.h>
#include <cstdint>

// NMS_5549097746496: fused 8x8x8 MaxPool -> MaxUnpool -> threshold(0.5) -> (thresholded == x)
// Input:  raw [2,3,128,256,256] fp32 ; Output: mask as float32 0/1.
//
// out[i] = (x[i]==0) ? 1 : 0 everywhere, EXCEPT the block-argmax position when
// bmax > 0.5, which is 1 (the unpooled value there is bit-identical to x).
// Phase 1 streams (x==0); phase 2 overwrites one element per hot window
// (same-thread program order -> correctly ordered).
//
// FINAL config (= R10, best measured: kernel 60.3us, DRAM 70.9%, wall 69.7us):
// burst-stage 16 independent LDG.128 (two dz-planes) before the store/compare
// pass. Explicit software pipelines (1-ahead and 2-ahead) both REGRESSED
// (R11: 63.5us, R12: 64.3us) at equal mapping/occupancy -- interleaving stores
// into the load window serializes the shared LSU issue path; the pure load
// burst is what maximizes read MLP. Occupancy 22-56% was shown not to matter.
//
// Layout (measured L1~42%): CTA = 128 thr = 4 warps; tile 8d x 8h x 256w.
//   warp : 0..3, owns a 64-float w-span (8 windows)
//   lane : win = lane>>2 (window), dzh = (lane>>1)&1 (dz half), wc = lane&1
// Per load instruction: 2 dz-planes x 256B contiguous = 4 fully-used 128B lines.

#define NMS_THRESH 0.5f

__global__ __launch_bounds__(128, 6)
void nms_mask_kernel(const float* __restrict__ in, float* __restrict__ out) {
    const int W = 256;
    const int HW = 256 * 256;

    int bid  = blockIdx.x;        // 6 * 16 * 32 = 3072
    int hblk = bid & 31;          // 32 h-windows
    int dblk = (bid >> 5) & 15;   // 16 d-windows
    int bc   = bid >> 9;          // 6

    int lane = threadIdx.x & 31;
    int warp = threadIdx.x >> 5;  // 0..3, w-span
    int win  = lane >> 2;         // 0..7  window within warp span
    int dzh  = (lane >> 1) & 1;   // 0..1  dz half (dz = dzh*4 + dzl)
    int wc   = lane & 1;          // 0..1  16B chunk within window row

    // window-origin offset (dz=0,dy=0,dx=0) for this lane's window
    size_t wbase = ((size_t)(bc * 128 + dblk * 8)) * HW
                 + (size_t)(hblk * 8) * W
                 + (size_t)(warp * 64 + win * 8);
    // this lane's chunk base
    size_t mybase = wbase + (size_t)dzh * 4 * HW + (size_t)wc * 4;

    const float* p = in  + mybase;
    float*       q = out + mybase;

    float best  = __int_as_float(0xff800000);  // -inf
    int   bestE = 1 << 30;

    #pragma unroll
    for (int half = 0; half < 2; half++) {
        const int dz0 = half * 2;   // planes dz0, dz0+1 of this dz-half

        // ---- stage two dz-planes: 16 independent LDG.128 (MLP=16) ----
        float4 v[2][8];
        #pragma unroll
        for (int pl = 0; pl < 2; pl++)
            #pragma unroll
            for (int dy = 0; dy < 8; dy++)
                v[pl][dy] = __ldcs(reinterpret_cast<const float4*>(
                                p + (dz0 + pl) * HW + dy * W));

        // ---- emit mask + update running (max, argE) ----
        #pragma unroll
        for (int pl = 0; pl < 2; pl++) {
            #pragma unroll
            for (int dy = 0; dy < 8; dy++) {
                float4 x = v[pl][dy];
                float4 m;
                m.x = (x.x == 0.0f) ? 1.0f : 0.0f;
                m.y = (x.y == 0.0f) ? 1.0f : 0.0f;
                m.z = (x.z == 0.0f) ? 1.0f : 0.0f;
                m.w = (x.w == 0.0f) ? 1.0f : 0.0f;
                __stcs(reinterpret_cast<float4*>(q + (dz0 + pl) * HW + dy * W), m);

                int eb = (dzh * 4 + dz0 + pl) * 64 + dy * 8 + wc * 4;  // K-index of x.x
                // full lexicographic comparator (value desc, e asc) -> order-independent
                if (x.x > best || (x.x == best && eb + 0 < bestE)) { best = x.x; bestE = eb + 0; }
                if (x.y > best || (x.y == best && eb + 1 < bestE)) { best = x.y; bestE = eb + 1; }
                if (x.z > best || (x.z == best && eb + 2 < bestE)) { best = x.z; bestE = eb + 2; }
                if (x.w > best || (x.w == best && eb + 3 < bestE)) { best = x.w; bestE = eb + 3; }
            }
        }
    }

    // remember local candidate to identify the owning lane afterwards
    float lbest = best; int lE = bestE;

    // reduce across the 4 lanes of this window (xor 1,2 stays in aligned group of 4)
    #pragma unroll
    for (int msk = 1; msk < 4; msk <<= 1) {
        float ov = __shfl_xor_sync(0xffffffffu, best,  msk);
        int   oe = __shfl_xor_sync(0xffffffffu, bestE, msk);
        if (ov > best || (ov == best && oe < bestE)) { best = ov; bestE = oe; }
    }

    // phase 2: the lane that loaded the winning element rewrites it to 1.0 if hot.
    // K-index e is unique across the window, so exactly one lane matches.
    if (best > NMS_THRESH && lbest == best && lE == bestE) {
        int dz = bestE >> 6, dy = (bestE >> 3) & 7, dx = bestE & 7;
        out[wbase + (size_t)dz * HW + (size_t)dy * W + dx] = 1.0f;
    }
}

extern "C" void kernel_launch(void* const* d_in, const int* in_sizes, int n_in,
                              void* d_out, int out_size) {
    (void)in_sizes; (void)n_in; (void)out_size;
    const float* in = (const float*)d_in[0];
    float* out = (float*)d_out;
    // bc(6) * dblk(16) * hblk(32) = 3072 CTAs, 128 threads each
    nms_mask_kernel<<<3072, 128>>>(in, out);
}